// round 16
// baseline (speedup 1.0000x reference)
#include <cuda_runtime.h>
#include <cuda_fp16.h>
#include <stdint.h>
#include <math.h>

// ---------------- problem dims ----------------
#define MDIM 8192      // B*S
#define HDIM 1024
#define RDIM 2048
#define SDIM 2048
#define NPROJ 12288    // 6 * 2048 stacked projection outputs (GEMM1 N)
#define PW 6144        // P width after pair fusion: f | q | gc
#define KOUT 4096      // R + L for the output GEMM
#define NCH 64         // scan chunks
#define CH 32          // tokens per chunk

// ---------------- scratch (device globals) ----------------
__device__ __half  g_P   [(size_t)MDIM * PW];              // f | q | gc (fp16)
__device__ __half  g_x16 [(size_t)MDIM * HDIM];
__device__ __half  g_w6  [(size_t)NPROJ * HDIM];
__device__ __half  g_wo  [(size_t)HDIM * KOUT];            // Wout single fp16
__device__ __half  g_a2  [(size_t)MDIM * KOUT];            // [ro | h], single fp16
__device__ float   g_Fc  [(size_t)4 * NCH * RDIM];
__device__ float   g_Gc  [(size_t)4 * NCH * RDIM];
__device__ float   g_Sc  [(size_t)4 * NCH * RDIM];

// ---------------- helpers ----------------
__device__ __forceinline__ uint32_t smem_u32(const void* p) {
    uint32_t a;
    asm("{ .reg .u64 t; cvta.to.shared.u64 t, %1; cvt.u32.u64 %0, t; }" : "=r"(a) : "l"(p));
    return a;
}
__device__ __forceinline__ void cp16(uint32_t s, const void* g) {
    asm volatile("cp.async.cg.shared.global [%0], [%1], 16;" :: "r"(s), "l"(g));
}
#define CP_COMMIT() asm volatile("cp.async.commit_group;" ::: "memory")
template<int N> __device__ __forceinline__ void cp_wait() {
    asm volatile("cp.async.wait_group %0;" :: "n"(N) : "memory");
}

__device__ __forceinline__ void ldm_x4(uint32_t (&d)[4], uint32_t a) {
    asm volatile("ldmatrix.sync.aligned.m8n8.x4.shared.b16 {%0,%1,%2,%3}, [%4];"
        : "=r"(d[0]), "=r"(d[1]), "=r"(d[2]), "=r"(d[3]) : "r"(a));
}
__device__ __forceinline__ void mma_f16(float (&c)[4], const uint32_t (&a)[4], const uint32_t* b) {
    asm volatile("mma.sync.aligned.m16n8k16.row.col.f32.f16.f16.f32 "
        "{%0,%1,%2,%3}, {%4,%5,%6,%7}, {%8,%9}, {%0,%1,%2,%3};"
        : "+f"(c[0]), "+f"(c[1]), "+f"(c[2]), "+f"(c[3])
        : "r"(a[0]), "r"(a[1]), "r"(a[2]), "r"(a[3]), "r"(b[0]), "r"(b[1]));
}

// ---------------- activations ----------------
#define ACT_NONE 0
#define ACT_TANH 1
#define ACT_GC 4     // pair: sigmoid(even) * silu(odd)   -> P (single col)
#define ACT_H  5     // pair: even * silu(odd)            -> a2 fp16

__device__ __forceinline__ float act_apply(float x, int act) {
    if (act == ACT_TANH) return tanhf(x);
    return x;
}
__device__ __forceinline__ float silu_f(float x) { return x / (1.0f + __expf(-x)); }
__device__ __forceinline__ float pair_act(float a, float b, int act) {
    if (act == ACT_GC) return (1.0f / (1.0f + __expf(-a))) * silu_f(b);
    return a * silu_f(b);   // ACT_H
}

#define BN 128
#define BM 64

// ---------------- shared epilogue (HOUT: fp16 C, else fp32 C) ----------------
template<bool HOUT>
__device__ __forceinline__ void epilogue_store(
    float (&acc)[4][4][4], int act, int bm, int bn, int colbase,
    int lane, int wn, void* Cv, int ldc, __half* aux)
{
    const int row0 = bm * BM + (lane >> 2);
    if (act < 4) {
        const int col0 = colbase + bn * BN + wn * 32 + 2 * (lane & 3);
#pragma unroll
        for (int mi = 0; mi < 4; mi++) {
#pragma unroll
            for (int nj = 0; nj < 4; nj++) {
                float a0 = act_apply(acc[mi][nj][0], act);
                float a1 = act_apply(acc[mi][nj][1], act);
                float a2v = act_apply(acc[mi][nj][2], act);
                float a3 = act_apply(acc[mi][nj][3], act);
                size_t base = (size_t)(row0 + mi * 16) * ldc + col0 + nj * 8;
                if (HOUT) {
                    __half* C = (__half*)Cv;
                    *(__half2*)(C + base)                   = __floats2half2_rn(a0, a1);
                    *(__half2*)(C + base + (size_t)8 * ldc) = __floats2half2_rn(a2v, a3);
                } else {
                    float* C = (float*)Cv;
                    float2 v0 = {a0, a1}, v1 = {a2v, a3};
                    *(float2*)(C + base)                   = v0;
                    *(float2*)(C + base + (size_t)8 * ldc) = v1;
                }
            }
        }
    } else {
        // pair regions: even/odd cols combined in-thread. Base from ACT
        // (gc/h each span TWO 2048-regions).
        __half* C = (__half*)Cv;
        const int pcbase = ((colbase + bn * BN) >> 1) - ((act == ACT_GC) ? 2048 : 4096);
        const int pc0 = pcbase + wn * 16 + (lane & 3);
#pragma unroll
        for (int mi = 0; mi < 4; mi++) {
#pragma unroll
            for (int nj = 0; nj < 4; nj++) {
                float v0 = pair_act(acc[mi][nj][0], acc[mi][nj][1], act);
                float v1 = pair_act(acc[mi][nj][2], acc[mi][nj][3], act);
                int pc = pc0 + nj * 4;
                int r  = row0 + mi * 16;
                if (act == ACT_GC) {
                    C[(size_t)r * ldc + 4096 + pc]       = __float2half_rn(v0);
                    C[(size_t)(r + 8) * ldc + 4096 + pc] = __float2half_rn(v1);
                } else {
                    aux[(size_t)r * KOUT + 2048 + pc]       = __float2half_rn(v0);
                    aux[(size_t)(r + 8) * KOUT + 2048 + pc] = __float2half_rn(v1);
                }
            }
        }
    }
}

// ================= slim 1-pass fp16 GEMM, templated KC =================
// C = act(A*B^T), single fp16 pass. KC_ HMMA-k per stage; OCC CTAs/SM.
template<int KC_, int OCC, bool HOUT>
__global__ void __launch_bounds__(128, OCC)
gemm_1p(const __half* __restrict__ A, const __half* __restrict__ B,
        int K, void* __restrict__ Cv, int ldc,
        __half* __restrict__ aux, unsigned actlut, int colbase)
{
    constexpr int RS  = KC_ * 2 + 16;                 // row stride bytes (+16B pad)
    constexpr uint32_t OFF_B = BM * RS;
    constexpr uint32_t SB    = (BM + 128) * RS;
    constexpr int CPR = KC_ / 8;                      // 16B chunks per row
    constexpr int RPS = 128 / CPR;                    // rows per cp.async sweep

    extern __shared__ char smem[];
    const uint32_t sbase = smem_u32(smem);
    const int tid = threadIdx.x;
    const int bm  = blockIdx.y, bn = blockIdx.x;
    const int wn  = tid >> 5, lane = tid & 31;

    const int region = (colbase + bn * BN) >> 11;
    const int act    = (int)((actlut >> (region * 4)) & 15u);

    const __half* sA = A + (size_t)bm * BM * K;
    const __half* sB = B + (size_t)bn * BN * K;

    const int lcol = tid & (CPR - 1), lrow0 = tid / CPR;

    auto load_stage = [&](int s) {
        const uint32_t sb = sbase + (uint32_t)(s & 1) * SB + lcol * 16;
        const int k0 = s * KC_ + lcol * 8;
#pragma unroll
        for (int i = 0; i < 64 / RPS; i++) {          // A: 64 rows
            int row = lrow0 + RPS * i;
            cp16(sb + row * RS, sA + (size_t)row * K + k0);
        }
#pragma unroll
        for (int i = 0; i < 128 / RPS; i++) {         // B: 128 rows
            int row = lrow0 + RPS * i;
            cp16(sb + OFF_B + row * RS, sB + (size_t)row * K + k0);
        }
    };

    const int quad = lane >> 3, r8 = lane & 7;
    const uint32_t aoff = (uint32_t)((r8 + (quad & 1) * 8) * RS + (quad >> 1) * 16);
    const uint32_t boff = (uint32_t)(OFF_B + (wn * 32 + r8 + (quad >> 1) * 8) * RS + (quad & 1) * 16);

    float acc[4][4][4];
#pragma unroll
    for (int mi = 0; mi < 4; mi++)
#pragma unroll
        for (int nj = 0; nj < 4; nj++)
#pragma unroll
            for (int e = 0; e < 4; e++) acc[mi][nj][e] = 0.0f;

    const int ns = K / KC_;
    load_stage(0); CP_COMMIT();

    for (int s = 0; s < ns; s++) {
        if (s + 1 < ns) load_stage(s + 1);
        CP_COMMIT();
        cp_wait<1>();
        __syncthreads();

        const uint32_t st = sbase + (uint32_t)(s & 1) * SB;
        const uint32_t aH = st + aoff;
        const uint32_t bH = st + boff;

#pragma unroll
        for (int ks = 0; ks < KC_ / 16; ks++) {
            const uint32_t kb = ks * 32;
            uint32_t afh[4][4], bf[4][2];
#pragma unroll
            for (int mi = 0; mi < 4; mi++) ldm_x4(afh[mi], aH + mi * (16 * RS) + kb);
#pragma unroll
            for (int t = 0; t < 2; t++) {
                uint32_t tt[4];
                ldm_x4(tt, bH + t * (16 * RS) + kb);
                bf[2 * t][0] = tt[0]; bf[2 * t][1] = tt[1];
                bf[2 * t + 1][0] = tt[2]; bf[2 * t + 1][1] = tt[3];
            }
#pragma unroll
            for (int mi = 0; mi < 4; mi++)
#pragma unroll
                for (int nj = 0; nj < 4; nj++) mma_f16(acc[mi][nj], afh[mi], bf[nj]);
        }
        __syncthreads();
    }

    epilogue_store<HOUT>(acc, act, bm, bn, colbase, lane, wn, Cv, ldc, aux);
}

// ================= conversion kernels (plain fp16 casts) =================
__global__ void conv_x_kernel(const float* __restrict__ x, __half* __restrict__ o) {
    size_t i = (size_t)blockIdx.x * blockDim.x + threadIdx.x;
    o[i] = __float2half_rn(x[i]);
}

// W6 stacking: [f(0:2048) | q(2048:4096) | g:c interleaved(4096:8192) | up:gate interleaved(8192:12288)]
__global__ void conv_w6_kernel(const float* __restrict__ Wf, const float* __restrict__ Wi,
                               const float* __restrict__ Wv, const float* __restrict__ Wq,
                               const float* __restrict__ Wup, const float* __restrict__ Wg,
                               __half* __restrict__ o) {
    size_t i = (size_t)blockIdx.x * blockDim.x + threadIdx.x;     // [0, 12288*1024)
    int n = (int)(i >> 10);
    int k = (int)(i & 1023);
    const float* src;
    int r;
    if (n < 2048)       { src = Wf; r = n; }
    else if (n < 4096)  { src = Wq; r = n - 2048; }
    else if (n < 8192)  { r = (n - 4096) >> 1; src = (n & 1) ? Wv : Wi; }
    else                { r = (n - 8192) >> 1; src = (n & 1) ? Wg : Wup; }
    o[i] = __float2half_rn(src[(size_t)r * 1024 + k]);
}

__global__ void conv_wout_kernel(const float* __restrict__ Wro, const float* __restrict__ Wd,
                                 __half* __restrict__ w) {
    size_t i = (size_t)blockIdx.x * blockDim.x + threadIdx.x;     // [0, 1024*4096)
    int h = (int)(i >> 12);
    int j = (int)(i & 4095);
    float v = (j < 2048) ? Wro[(size_t)h * 2048 + j] : Wd[(size_t)h * 2048 + (j - 2048)];
    w[i] = __float2half_rn(v);
}

// ================= scan (two-level, chunked; P is fp16) =================
// P cols: f[0:2048)  q[2048:4096)  gc[4096:6144)
__global__ void scanA_kernel(const __half* __restrict__ P,
                             float* __restrict__ Fc, float* __restrict__ Gc) {
    int r  = blockIdx.x * blockDim.x + threadIdx.x;
    int bc = blockIdx.y;
    int b = bc >> 6, ch = bc & 63;
    const __half* row = P + (size_t)(b * SDIM + ch * CH) * PW;
    float F = 1.0f, G = 0.0f;
#pragma unroll 4
    for (int t = 0; t < CH; t++) {
        float f  = __half2float(row[r]);
        float gc = __half2float(row[4096 + r]);
        G = fmaf(f, G, gc);
        F *= f;
        row += PW;
    }
    Fc[(size_t)bc * RDIM + r] = F;
    Gc[(size_t)bc * RDIM + r] = G;
}

__global__ void scanB_kernel(const float* __restrict__ Fc, const float* __restrict__ Gc,
                             const float* __restrict__ init, float* __restrict__ Sc) {
    int i = blockIdx.x * blockDim.x + threadIdx.x;
    int b = i >> 11, r = i & 2047;
    float state = init[r];
    for (int ch = 0; ch < NCH; ch++) {
        size_t idx = (size_t)(b * NCH + ch) * RDIM + r;
        Sc[idx] = state;
        state = fmaf(Fc[idx], state, Gc[idx]);
    }
}

__global__ void scanC_kernel(const __half* __restrict__ P, const float* __restrict__ Sc,
                             __half* __restrict__ a2) {
    int r  = blockIdx.x * blockDim.x + threadIdx.x;
    int bc = blockIdx.y;
    int b = bc >> 6, ch = bc & 63;
    int m0 = b * SDIM + ch * CH;
    const __half* row = P + (size_t)m0 * PW;
    float state = Sc[(size_t)bc * RDIM + r];
#pragma unroll 4
    for (int t = 0; t < CH; t++) {
        float f  = __half2float(row[r]);
        float q  = __half2float(row[2048 + r]);
        float gc = __half2float(row[4096 + r]);
        state = fmaf(f, state, gc);
        float z = q * state;
        float ro = z / (1.0f + __expf(-z));
        a2[(size_t)(m0 + t) * KOUT + r] = __float2half_rn(ro);
        row += PW;
    }
}

// ================= launch =================
extern "C" void kernel_launch(void* const* d_in, const int* in_sizes, int n_in,
                              void* d_out, int out_size)
{
    const float* x    = (const float*)d_in[0];
    const float* Wf   = (const float*)d_in[1];
    const float* Wi   = (const float*)d_in[2];
    const float* Wv   = (const float*)d_in[3];
    const float* Wq   = (const float*)d_in[4];
    const float* Wro  = (const float*)d_in[5];
    const float* Wup  = (const float*)d_in[6];
    const float* Wg   = (const float*)d_in[7];
    const float* Wd   = (const float*)d_in[8];
    const float* init = (const float*)d_in[9];
    float* out = (float*)d_out;

    float *pFc, *pGc, *pSc;
    __half *pP, *px16, *pw6, *pwo, *pa2;
    cudaGetSymbolAddress((void**)&pP,   g_P);
    cudaGetSymbolAddress((void**)&px16, g_x16);
    cudaGetSymbolAddress((void**)&pw6,  g_w6);
    cudaGetSymbolAddress((void**)&pwo,  g_wo);
    cudaGetSymbolAddress((void**)&pa2,  g_a2);
    cudaGetSymbolAddress((void**)&pFc,  g_Fc);
    cudaGetSymbolAddress((void**)&pGc,  g_Gc);
    cudaGetSymbolAddress((void**)&pSc,  g_Sc);

    // GEMM1: KC=64, OCC=4 (proven). Stage (64+128)*144 = 27648; x2 = 55296.
    // GEMM2: KC=128, OCC=2. Stage (64+128)*272 = 52224; x2 = 104448.
    const int SMEM_G1 = (BM + 128) * (64 * 2 + 16) * 2;
    const int SMEM_G2 = (BM + 128) * (128 * 2 + 16) * 2;
    cudaFuncSetAttribute((const void*)gemm_1p<64, 4, true>,
                         cudaFuncAttributeMaxDynamicSharedMemorySize, SMEM_G1);
    cudaFuncSetAttribute((const void*)gemm_1p<128, 2, false>,
                         cudaFuncAttributeMaxDynamicSharedMemorySize, SMEM_G2);

    // conversions (plain casts)
    conv_x_kernel   <<<(MDIM * HDIM) / 256, 256>>>(x, px16);
    conv_w6_kernel  <<<(NPROJ * HDIM) / 256, 256>>>(Wf, Wi, Wv, Wq, Wup, Wg, pw6);
    conv_wout_kernel<<<(HDIM * KOUT) / 256, 256>>>(Wro, Wd, pwo);

    // GEMM1: all regions 1-pass. actlut nibbles: f=1(tanh) q=0 gc=4,4 h=5,5 -> 0x554401
    {
        dim3 grid(NPROJ / BN, MDIM / BM);   // (96, 128)
        gemm_1p<64, 4, true><<<grid, 128, SMEM_G1>>>(px16, pw6, HDIM, pP, PW,
                                                     pa2, 0x554401u, 0);
    }

    // scan
    {
        dim3 gA(RDIM / 256, 4 * NCH);
        scanA_kernel<<<gA, 256>>>(pP, pFc, pGc);
        scanB_kernel<<<32, 256>>>(pFc, pGc, init, pSc);
        scanC_kernel<<<gA, 256>>>(pP, pSc, pa2);
    }

    // GEMM2: out = [ro | h] @ Wout^T, single-pass fp16, KC=128
    {
        dim3 grid(HDIM / BN, MDIM / BM);    // (8, 128)
        gemm_1p<128, 2, false><<<grid, 128, SMEM_G2>>>(pa2, pwo, KOUT, out, HDIM,
                                                       pa2, 0u, 0);
    }
}

// round 17
// speedup vs baseline: 1.0428x; 1.0428x over previous
#include <cuda_runtime.h>
#include <cuda_fp16.h>
#include <stdint.h>
#include <math.h>

// ---------------- problem dims ----------------
#define MDIM 8192      // B*S
#define HDIM 1024
#define RDIM 2048
#define SDIM 2048
#define NPROJ 12288    // 6 * 2048 stacked projection outputs (GEMM1 N)
#define PW 6144        // P width after pair fusion: f | q | gc
#define KOUT 4096      // R + L for the output GEMM
#define NCH 64         // scan chunks
#define CH 32          // tokens per chunk

// ---------------- scratch (device globals) ----------------
__device__ __half  g_P   [(size_t)MDIM * PW];              // f | q | gc (fp16)
__device__ __half  g_x16 [(size_t)MDIM * HDIM];
__device__ __half  g_w6  [(size_t)NPROJ * HDIM];
__device__ __half  g_wo  [(size_t)HDIM * KOUT];            // Wout single fp16
__device__ __half  g_a2  [(size_t)MDIM * KOUT];            // [ro | h], single fp16
__device__ float   g_Fc  [(size_t)4 * NCH * RDIM];
__device__ float   g_Gc  [(size_t)4 * NCH * RDIM];
__device__ float   g_Sc  [(size_t)4 * NCH * RDIM];

// ---------------- helpers ----------------
__device__ __forceinline__ uint32_t smem_u32(const void* p) {
    uint32_t a;
    asm("{ .reg .u64 t; cvta.to.shared.u64 t, %1; cvt.u32.u64 %0, t; }" : "=r"(a) : "l"(p));
    return a;
}
__device__ __forceinline__ void cp16(uint32_t s, const void* g) {
    asm volatile("cp.async.cg.shared.global [%0], [%1], 16;" :: "r"(s), "l"(g));
}
#define CP_COMMIT() asm volatile("cp.async.commit_group;" ::: "memory")
template<int N> __device__ __forceinline__ void cp_wait() {
    asm volatile("cp.async.wait_group %0;" :: "n"(N) : "memory");
}

__device__ __forceinline__ void ldm_x4(uint32_t (&d)[4], uint32_t a) {
    asm volatile("ldmatrix.sync.aligned.m8n8.x4.shared.b16 {%0,%1,%2,%3}, [%4];"
        : "=r"(d[0]), "=r"(d[1]), "=r"(d[2]), "=r"(d[3]) : "r"(a));
}
__device__ __forceinline__ void mma_f16(float (&c)[4], const uint32_t (&a)[4], const uint32_t* b) {
    asm volatile("mma.sync.aligned.m16n8k16.row.col.f32.f16.f16.f32 "
        "{%0,%1,%2,%3}, {%4,%5,%6,%7}, {%8,%9}, {%0,%1,%2,%3};"
        : "+f"(c[0]), "+f"(c[1]), "+f"(c[2]), "+f"(c[3])
        : "r"(a[0]), "r"(a[1]), "r"(a[2]), "r"(a[3]), "r"(b[0]), "r"(b[1]));
}

// ---------------- activations ----------------
#define ACT_NONE 0
#define ACT_TANH 1
#define ACT_GC 4     // pair: sigmoid(even) * silu(odd)   -> P (single col)
#define ACT_H  5     // pair: even * silu(odd)            -> a2 fp16

__device__ __forceinline__ float act_apply(float x, int act) {
    if (act == ACT_TANH) return tanhf(x);
    return x;
}
__device__ __forceinline__ float silu_f(float x) { return x / (1.0f + __expf(-x)); }
__device__ __forceinline__ float pair_act(float a, float b, int act) {
    if (act == ACT_GC) return (1.0f / (1.0f + __expf(-a))) * silu_f(b);
    return a * silu_f(b);   // ACT_H
}

#define BN 128
#define BM 64

// ---------------- shared epilogue (HOUT: fp16 C, else fp32 C) ----------------
template<bool HOUT>
__device__ __forceinline__ void epilogue_store(
    float (&acc)[4][4][4], int act, int bm, int bn, int colbase,
    int lane, int wn, void* Cv, int ldc, __half* aux)
{
    const int row0 = bm * BM + (lane >> 2);
    if (act < 4) {
        const int col0 = colbase + bn * BN + wn * 32 + 2 * (lane & 3);
#pragma unroll
        for (int mi = 0; mi < 4; mi++) {
#pragma unroll
            for (int nj = 0; nj < 4; nj++) {
                float a0 = act_apply(acc[mi][nj][0], act);
                float a1 = act_apply(acc[mi][nj][1], act);
                float a2v = act_apply(acc[mi][nj][2], act);
                float a3 = act_apply(acc[mi][nj][3], act);
                size_t base = (size_t)(row0 + mi * 16) * ldc + col0 + nj * 8;
                if (HOUT) {
                    __half* C = (__half*)Cv;
                    *(__half2*)(C + base)                   = __floats2half2_rn(a0, a1);
                    *(__half2*)(C + base + (size_t)8 * ldc) = __floats2half2_rn(a2v, a3);
                } else {
                    float* C = (float*)Cv;
                    float2 v0 = {a0, a1}, v1 = {a2v, a3};
                    *(float2*)(C + base)                   = v0;
                    *(float2*)(C + base + (size_t)8 * ldc) = v1;
                }
            }
        }
    } else {
        // pair regions: even/odd cols combined in-thread. Base from ACT
        // (gc/h each span TWO 2048-regions).
        __half* C = (__half*)Cv;
        const int pcbase = ((colbase + bn * BN) >> 1) - ((act == ACT_GC) ? 2048 : 4096);
        const int pc0 = pcbase + wn * 16 + (lane & 3);
#pragma unroll
        for (int mi = 0; mi < 4; mi++) {
#pragma unroll
            for (int nj = 0; nj < 4; nj++) {
                float v0 = pair_act(acc[mi][nj][0], acc[mi][nj][1], act);
                float v1 = pair_act(acc[mi][nj][2], acc[mi][nj][3], act);
                int pc = pc0 + nj * 4;
                int r  = row0 + mi * 16;
                if (act == ACT_GC) {
                    C[(size_t)r * ldc + 4096 + pc]       = __float2half_rn(v0);
                    C[(size_t)(r + 8) * ldc + 4096 + pc] = __float2half_rn(v1);
                } else {
                    aux[(size_t)r * KOUT + 2048 + pc]       = __float2half_rn(v0);
                    aux[(size_t)(r + 8) * KOUT + 2048 + pc] = __float2half_rn(v1);
                }
            }
        }
    }
}

// ================= slim 1-pass fp16 GEMM, templated KC =================
// C = act(A*B^T), single fp16 pass. KC_ HMMA-k per stage; OCC CTAs/SM.
template<int KC_, int OCC, bool HOUT>
__global__ void __launch_bounds__(128, OCC)
gemm_1p(const __half* __restrict__ A, const __half* __restrict__ B,
        int K, void* __restrict__ Cv, int ldc,
        __half* __restrict__ aux, unsigned actlut, int colbase)
{
    constexpr int RS  = KC_ * 2 + 16;                 // row stride bytes (+16B pad)
    constexpr uint32_t OFF_B = BM * RS;
    constexpr uint32_t SB    = (BM + 128) * RS;
    constexpr int CPR = KC_ / 8;                      // 16B chunks per row
    constexpr int RPS = 128 / CPR;                    // rows per cp.async sweep

    extern __shared__ char smem[];
    const uint32_t sbase = smem_u32(smem);
    const int tid = threadIdx.x;
    const int bm  = blockIdx.y, bn = blockIdx.x;
    const int wn  = tid >> 5, lane = tid & 31;

    const int region = (colbase + bn * BN) >> 11;
    const int act    = (int)((actlut >> (region * 4)) & 15u);

    const __half* sA = A + (size_t)bm * BM * K;
    const __half* sB = B + (size_t)bn * BN * K;

    const int lcol = tid & (CPR - 1), lrow0 = tid / CPR;

    auto load_stage = [&](int s) {
        const uint32_t sb = sbase + (uint32_t)(s & 1) * SB + lcol * 16;
        const int k0 = s * KC_ + lcol * 8;
#pragma unroll
        for (int i = 0; i < 64 / RPS; i++) {          // A: 64 rows
            int row = lrow0 + RPS * i;
            cp16(sb + row * RS, sA + (size_t)row * K + k0);
        }
#pragma unroll
        for (int i = 0; i < 128 / RPS; i++) {         // B: 128 rows
            int row = lrow0 + RPS * i;
            cp16(sb + OFF_B + row * RS, sB + (size_t)row * K + k0);
        }
    };

    const int quad = lane >> 3, r8 = lane & 7;
    const uint32_t aoff = (uint32_t)((r8 + (quad & 1) * 8) * RS + (quad >> 1) * 16);
    const uint32_t boff = (uint32_t)(OFF_B + (wn * 32 + r8 + (quad >> 1) * 8) * RS + (quad & 1) * 16);

    float acc[4][4][4];
#pragma unroll
    for (int mi = 0; mi < 4; mi++)
#pragma unroll
        for (int nj = 0; nj < 4; nj++)
#pragma unroll
            for (int e = 0; e < 4; e++) acc[mi][nj][e] = 0.0f;

    const int ns = K / KC_;
    load_stage(0); CP_COMMIT();

    for (int s = 0; s < ns; s++) {
        if (s + 1 < ns) load_stage(s + 1);
        CP_COMMIT();
        cp_wait<1>();
        __syncthreads();

        const uint32_t st = sbase + (uint32_t)(s & 1) * SB;
        const uint32_t aH = st + aoff;
        const uint32_t bH = st + boff;

#pragma unroll
        for (int ks = 0; ks < KC_ / 16; ks++) {
            const uint32_t kb = ks * 32;
            uint32_t afh[4][4], bf[4][2];
#pragma unroll
            for (int mi = 0; mi < 4; mi++) ldm_x4(afh[mi], aH + mi * (16 * RS) + kb);
#pragma unroll
            for (int t = 0; t < 2; t++) {
                uint32_t tt[4];
                ldm_x4(tt, bH + t * (16 * RS) + kb);
                bf[2 * t][0] = tt[0]; bf[2 * t][1] = tt[1];
                bf[2 * t + 1][0] = tt[2]; bf[2 * t + 1][1] = tt[3];
            }
#pragma unroll
            for (int mi = 0; mi < 4; mi++)
#pragma unroll
                for (int nj = 0; nj < 4; nj++) mma_f16(acc[mi][nj], afh[mi], bf[nj]);
        }
        __syncthreads();
    }

    epilogue_store<HOUT>(acc, act, bm, bn, colbase, lane, wn, Cv, ldc, aux);
}

// ================= conversion kernels (plain fp16 casts) =================
__global__ void conv_x_kernel(const float* __restrict__ x, __half* __restrict__ o) {
    size_t i = (size_t)blockIdx.x * blockDim.x + threadIdx.x;
    o[i] = __float2half_rn(x[i]);
}

// W6 stacking: [f(0:2048) | q(2048:4096) | g:c interleaved(4096:8192) | up:gate interleaved(8192:12288)]
__global__ void conv_w6_kernel(const float* __restrict__ Wf, const float* __restrict__ Wi,
                               const float* __restrict__ Wv, const float* __restrict__ Wq,
                               const float* __restrict__ Wup, const float* __restrict__ Wg,
                               __half* __restrict__ o) {
    size_t i = (size_t)blockIdx.x * blockDim.x + threadIdx.x;     // [0, 12288*1024)
    int n = (int)(i >> 10);
    int k = (int)(i & 1023);
    const float* src;
    int r;
    if (n < 2048)       { src = Wf; r = n; }
    else if (n < 4096)  { src = Wq; r = n - 2048; }
    else if (n < 8192)  { r = (n - 4096) >> 1; src = (n & 1) ? Wv : Wi; }
    else                { r = (n - 8192) >> 1; src = (n & 1) ? Wg : Wup; }
    o[i] = __float2half_rn(src[(size_t)r * 1024 + k]);
}

__global__ void conv_wout_kernel(const float* __restrict__ Wro, const float* __restrict__ Wd,
                                 __half* __restrict__ w) {
    size_t i = (size_t)blockIdx.x * blockDim.x + threadIdx.x;     // [0, 1024*4096)
    int h = (int)(i >> 12);
    int j = (int)(i & 4095);
    float v = (j < 2048) ? Wro[(size_t)h * 2048 + j] : Wd[(size_t)h * 2048 + (j - 2048)];
    w[i] = __float2half_rn(v);
}

// ================= scan (two-level, chunked; P is fp16) =================
// P cols: f[0:2048)  q[2048:4096)  gc[4096:6144)
__global__ void scanA_kernel(const __half* __restrict__ P,
                             float* __restrict__ Fc, float* __restrict__ Gc) {
    int r  = blockIdx.x * blockDim.x + threadIdx.x;
    int bc = blockIdx.y;
    int b = bc >> 6, ch = bc & 63;
    const __half* row = P + (size_t)(b * SDIM + ch * CH) * PW;
    float F = 1.0f, G = 0.0f;
#pragma unroll 4
    for (int t = 0; t < CH; t++) {
        float f  = __half2float(row[r]);
        float gc = __half2float(row[4096 + r]);
        G = fmaf(f, G, gc);
        F *= f;
        row += PW;
    }
    Fc[(size_t)bc * RDIM + r] = F;
    Gc[(size_t)bc * RDIM + r] = G;
}

__global__ void scanB_kernel(const float* __restrict__ Fc, const float* __restrict__ Gc,
                             const float* __restrict__ init, float* __restrict__ Sc) {
    int i = blockIdx.x * blockDim.x + threadIdx.x;
    int b = i >> 11, r = i & 2047;
    float state = init[r];
    for (int ch = 0; ch < NCH; ch++) {
        size_t idx = (size_t)(b * NCH + ch) * RDIM + r;
        Sc[idx] = state;
        state = fmaf(Fc[idx], state, Gc[idx]);
    }
}

__global__ void scanC_kernel(const __half* __restrict__ P, const float* __restrict__ Sc,
                             __half* __restrict__ a2) {
    int r  = blockIdx.x * blockDim.x + threadIdx.x;
    int bc = blockIdx.y;
    int b = bc >> 6, ch = bc & 63;
    int m0 = b * SDIM + ch * CH;
    const __half* row = P + (size_t)m0 * PW;
    float state = Sc[(size_t)bc * RDIM + r];
#pragma unroll 4
    for (int t = 0; t < CH; t++) {
        float f  = __half2float(row[r]);
        float q  = __half2float(row[2048 + r]);
        float gc = __half2float(row[4096 + r]);
        state = fmaf(f, state, gc);
        float z = q * state;
        float ro = z / (1.0f + __expf(-z));
        a2[(size_t)(m0 + t) * KOUT + r] = __float2half_rn(ro);
        row += PW;
    }
}

// ================= launch =================
extern "C" void kernel_launch(void* const* d_in, const int* in_sizes, int n_in,
                              void* d_out, int out_size)
{
    const float* x    = (const float*)d_in[0];
    const float* Wf   = (const float*)d_in[1];
    const float* Wi   = (const float*)d_in[2];
    const float* Wv   = (const float*)d_in[3];
    const float* Wq   = (const float*)d_in[4];
    const float* Wro  = (const float*)d_in[5];
    const float* Wup  = (const float*)d_in[6];
    const float* Wg   = (const float*)d_in[7];
    const float* Wd   = (const float*)d_in[8];
    const float* init = (const float*)d_in[9];
    float* out = (float*)d_out;

    float *pFc, *pGc, *pSc;
    __half *pP, *px16, *pw6, *pwo, *pa2;
    cudaGetSymbolAddress((void**)&pP,   g_P);
    cudaGetSymbolAddress((void**)&px16, g_x16);
    cudaGetSymbolAddress((void**)&pw6,  g_w6);
    cudaGetSymbolAddress((void**)&pwo,  g_wo);
    cudaGetSymbolAddress((void**)&pa2,  g_a2);
    cudaGetSymbolAddress((void**)&pFc,  g_Fc);
    cudaGetSymbolAddress((void**)&pGc,  g_Gc);
    cudaGetSymbolAddress((void**)&pSc,  g_Sc);

    // Both GEMMs: KC=64, OCC=4 (proven config). Stage (64+128)*144 = 27648; x2 = 55296.
    const int SMEM_G = (BM + 128) * (64 * 2 + 16) * 2;
    cudaFuncSetAttribute((const void*)gemm_1p<64, 4, true>,
                         cudaFuncAttributeMaxDynamicSharedMemorySize, SMEM_G);
    cudaFuncSetAttribute((const void*)gemm_1p<64, 4, false>,
                         cudaFuncAttributeMaxDynamicSharedMemorySize, SMEM_G);

    // conversions (plain casts)
    conv_x_kernel   <<<(MDIM * HDIM) / 256, 256>>>(x, px16);
    conv_w6_kernel  <<<(NPROJ * HDIM) / 256, 256>>>(Wf, Wi, Wv, Wq, Wup, Wg, pw6);
    conv_wout_kernel<<<(HDIM * KOUT) / 256, 256>>>(Wro, Wd, pwo);

    // GEMM1: all regions 1-pass. actlut nibbles: f=1(tanh) q=0 gc=4,4 h=5,5 -> 0x554401
    {
        dim3 grid(NPROJ / BN, MDIM / BM);   // (96, 128)
        gemm_1p<64, 4, true><<<grid, 128, SMEM_G>>>(px16, pw6, HDIM, pP, PW,
                                                    pa2, 0x554401u, 0);
    }

    // scan
    {
        dim3 gA(RDIM / 256, 4 * NCH);
        scanA_kernel<<<gA, 256>>>(pP, pFc, pGc);
        scanB_kernel<<<32, 256>>>(pFc, pGc, init, pSc);
        scanC_kernel<<<gA, 256>>>(pP, pSc, pa2);
    }

    // GEMM2: out = [ro | h] @ Wout^T, single-pass fp16, KC=64 OCC=4
    {
        dim3 grid(HDIM / BN, MDIM / BM);    // (8, 128)
        gemm_1p<64, 4, false><<<grid, 128, SMEM_G>>>(pa2, pwo, KOUT, out, HDIM,
                                                     pa2, 0u, 0);
    }
}